// round 5
// baseline (speedup 1.0000x reference)
#include <cuda_runtime.h>
#include <cuda_bf16.h>

#define NN 100000
#define EE 1000000
#define IN_N 128
#define IN_E 64
#define HFC 128   // H*F = 4*32 = 128 for both node and edge projections

// ---- scratch (static device allocations are the allowed mechanism) ----
__device__ float    g_fni[(size_t)NN * HFC];   // nfeats @ W_ni
__device__ float    g_fnj[(size_t)NN * HFC];   // nfeats @ W_nj
__device__ float    g_h  [(size_t)NN * HFC];   // nfeats @ W_node + b
__device__ float    g_ex [(size_t)EE * 4];     // logits, then exp(logit - max)
__device__ unsigned g_m  [(size_t)NN * 4];     // segment max (order-preserving uint)
__device__ float    g_s  [(size_t)NN * 4];     // segment sum

// order-preserving float<->uint transform for unsigned atomicMax
__device__ __forceinline__ unsigned ford(float f) {
    unsigned b = __float_as_uint(f);
    return (b & 0x80000000u) ? ~b : (b | 0x80000000u);
}
__device__ __forceinline__ float unford(unsigned u) {
    return __uint_as_float((u & 0x80000000u) ? (u & 0x7fffffffu) : ~u);
}

__device__ __forceinline__ void red_add_v4(float* p, float4 v) {
    asm volatile("red.global.add.v4.f32 [%0], {%1,%2,%3,%4};"
                 :: "l"(p), "f"(v.x), "f"(v.y), "f"(v.z), "f"(v.w) : "memory");
}

// ---------------------------------------------------------------------------
// 0) zero h_out region, g_s, g_m
// ---------------------------------------------------------------------------
__global__ void init_kernel(float* __restrict__ hout, int N) {
    int stride = gridDim.x * blockDim.x;
    int i = blockIdx.x * blockDim.x + threadIdx.x;
    int n4 = N * 4;
    for (int j = i; j < n4; j += stride) { g_m[j] = 0u; g_s[j] = 0.0f; }
    int nh = N * HFC;
    for (int j = i; j < nh; j += stride) hout[j] = 0.0f;
}

// ---------------------------------------------------------------------------
// 1) node projections: f_ni, f_nj, h  (three 128x128 GEMMs fused)
//    block = 128 threads (one output column each), 32 nodes per block
// ---------------------------------------------------------------------------
__global__ __launch_bounds__(128) void node_proj(
    const float* __restrict__ x,
    const float* __restrict__ Wni, const float* __restrict__ Wnj,
    const float* __restrict__ Wn,  const float* __restrict__ bn, int N)
{
    __shared__ float xs[32 * IN_N];
    const int c = threadIdx.x;
    const int base = blockIdx.x * 32;
    const int nrows = min(32, N - base);

    // stage node tile in shared
    {
        const float4* xg = (const float4*)(x + (size_t)base * IN_N);
        float4* xs4 = (float4*)xs;
        int tot4 = nrows * (IN_N / 4);
        for (int i = c; i < tot4; i += 128) xs4[i] = xg[i];
    }
    __syncthreads();

    #pragma unroll
    for (int m = 0; m < 3; m++) {
        const float* W = (m == 0) ? Wni : (m == 1) ? Wnj : Wn;
        float* O       = (m == 0) ? g_fni : (m == 1) ? g_fnj : g_h;
        float bias = (m == 2) ? bn[c] : 0.0f;

        for (int g = 0; g < 32; g += 16) {
            float acc[16];
            #pragma unroll
            for (int i = 0; i < 16; i++) acc[i] = bias;

            #pragma unroll 4
            for (int k = 0; k < IN_N; k += 4) {
                float w0 = W[(k + 0) * HFC + c];
                float w1 = W[(k + 1) * HFC + c];
                float w2 = W[(k + 2) * HFC + c];
                float w3 = W[(k + 3) * HFC + c];
                #pragma unroll
                for (int i = 0; i < 16; i++) {
                    float4 xv = *(const float4*)&xs[(g + i) * IN_N + k];
                    acc[i] = fmaf(xv.x, w0, acc[i]);
                    acc[i] = fmaf(xv.y, w1, acc[i]);
                    acc[i] = fmaf(xv.z, w2, acc[i]);
                    acc[i] = fmaf(xv.w, w3, acc[i]);
                }
            }
            int gn = min(16, nrows - g);
            for (int i = 0; i < gn; i++)
                O[(size_t)(base + g + i) * HFC + c] = acc[i];
        }
    }
}

// ---------------------------------------------------------------------------
// 2) per-edge: f_out = lrelu(f_ni[src] + f_nj[dst] + efeats@W_fij + bias),
//    write f_out, logits e[e][h], atomicMax per (dst, head)
//    W_fij column kept in registers (64 regs/thread), persistent grid
// ---------------------------------------------------------------------------
#define EPB1 8
__global__ __launch_bounds__(128) void edge_pass1(
    const float* __restrict__ ef, const int* __restrict__ src,
    const int* __restrict__ dst, const float* __restrict__ Wf,
    const float* __restrict__ attn, const float* __restrict__ bias,
    float* __restrict__ fout, int E)
{
    const int c = threadIdx.x;
    const int head = c >> 5;
    const int lane = c & 31;

    float wcol[IN_E];
    #pragma unroll
    for (int k = 0; k < IN_E; k++) wcol[k] = Wf[k * HFC + c];
    const float av = attn[head * 32 + lane];
    const float bv = bias[c];

    __shared__ float efs[EPB1][IN_E];

    for (long long e0 = (long long)blockIdx.x * EPB1; e0 < E;
         e0 += (long long)gridDim.x * EPB1) {
        int ne = (int)min((long long)EPB1, (long long)E - e0);
        __syncthreads();
        // stage edge-feature rows (ne*64 floats = ne*16 float4)
        for (int i = c; i < ne * (IN_E / 4); i += 128) {
            int j = i >> 4, k4 = i & 15;
            ((float4*)efs[j])[k4] =
                ((const float4*)(ef + (size_t)(e0 + j) * IN_E))[k4];
        }
        __syncthreads();

        float acc[EPB1];
        #pragma unroll
        for (int j = 0; j < EPB1; j++) acc[j] = bv;

        #pragma unroll
        for (int k = 0; k < IN_E; k += 4) {
            #pragma unroll
            for (int j = 0; j < EPB1; j++) {
                float4 xv = *(const float4*)&efs[j][k];
                acc[j] = fmaf(xv.x, wcol[k + 0], acc[j]);
                acc[j] = fmaf(xv.y, wcol[k + 1], acc[j]);
                acc[j] = fmaf(xv.z, wcol[k + 2], acc[j]);
                acc[j] = fmaf(xv.w, wcol[k + 3], acc[j]);
            }
        }

        for (int j = 0; j < ne; j++) {
            long long e = e0 + j;
            int s = src[e], d = dst[e];
            float v = acc[j] + g_fni[(size_t)s * HFC + c]
                            + g_fnj[(size_t)d * HFC + c];
            v = (v > 0.0f) ? v : 0.01f * v;               // leaky relu
            fout[(size_t)e * HFC + c] = v;
            float t = v * av;                              // attn logit
            #pragma unroll
            for (int o = 16; o > 0; o >>= 1)
                t += __shfl_xor_sync(0xffffffffu, t, o);
            if (lane == 0) {
                g_ex[e * 4 + head] = t;
                atomicMax(&g_m[(size_t)d * 4 + head], ford(t));
            }
        }
    }
}

// ---------------------------------------------------------------------------
// 3) ex = exp(e - m[dst]); segment sum
// ---------------------------------------------------------------------------
__global__ void pass2(const int* __restrict__ dst, int E) {
    int i = blockIdx.x * blockDim.x + threadIdx.x;
    int tot = E * 4;
    if (i >= tot) return;
    int e = i >> 2, h = i & 3;
    int d = dst[e];
    float m = unford(g_m[(size_t)d * 4 + h]);
    float ex = __expf(g_ex[i] - m);
    g_ex[i] = ex;
    atomicAdd(&g_s[(size_t)d * 4 + h], ex);
}

// ---------------------------------------------------------------------------
// 4) a = ex/s[dst]; h_out[dst] += h[src]*a  (vector RED, warp per edge)
// ---------------------------------------------------------------------------
#define EPB3 8
__global__ __launch_bounds__(128) void pass3(
    const int* __restrict__ src, const int* __restrict__ dst,
    float* __restrict__ hout, int E)
{
    const int warp = threadIdx.x >> 5;
    const int lane = threadIdx.x & 31;
    const int head = lane >> 3;                 // lane*4 feats -> head = lane/8
    long long base = (long long)blockIdx.x * EPB3;
    #pragma unroll
    for (int r = 0; r < EPB3 / 4; r++) {
        long long e = base + r * 4 + warp;
        if (e >= E) return;
        int s = src[e], d = dst[e];
        float a = g_ex[e * 4 + head] / g_s[(size_t)d * 4 + head];
        float4 hv = ((const float4*)(g_h + (size_t)s * HFC))[lane];
        float4 v = make_float4(hv.x * a, hv.y * a, hv.z * a, hv.w * a);
        red_add_v4(hout + (size_t)d * HFC + lane * 4, v);
    }
}

// ---------------------------------------------------------------------------
extern "C" void kernel_launch(void* const* d_in, const int* in_sizes, int n_in,
                              void* d_out, int out_size)
{
    const float* nfeats = (const float*)d_in[0];
    const float* efeats = (const float*)d_in[1];
    const int*   src    = (const int*)d_in[2];
    const int*   dst    = (const int*)d_in[3];
    const float* W_node = (const float*)d_in[4];
    const float* b_node = (const float*)d_in[5];
    const float* W_ni   = (const float*)d_in[6];
    const float* W_nj   = (const float*)d_in[7];
    const float* W_fij  = (const float*)d_in[8];
    const float* attn   = (const float*)d_in[9];
    const float* bias   = (const float*)d_in[10];

    const int N = in_sizes[0] / IN_N;   // 100000
    const int E = in_sizes[2];          // 1000000

    float* h_out = (float*)d_out;                       // [N, 128]
    float* f_out = (float*)d_out + (size_t)N * HFC;     // [E, 128]

    init_kernel<<<1024, 256>>>(h_out, N);

    node_proj<<<(N + 31) / 32, 128>>>(nfeats, W_ni, W_nj, W_node, b_node, N);

    edge_pass1<<<148 * 8, 128>>>(efeats, src, dst, W_fij, attn, bias, f_out, E);

    pass2<<<(E * 4 + 255) / 256, 256>>>(dst, E);

    pass3<<<(E + EPB3 - 1) / EPB3, 128>>>(src, dst, h_out, E);
}

// round 6
// speedup vs baseline: 1.3475x; 1.3475x over previous
#include <cuda_runtime.h>
#include <cuda_bf16.h>

#define NN 100000
#define EE 1000000
#define IN_N 128
#define IN_E 64
#define HFC 128   // H*F = 4*32 = 128 for both node and edge projections

// ---- scratch (static device allocations are the allowed mechanism) ----
__device__ float    g_fni[(size_t)NN * HFC];   // nfeats @ W_ni
__device__ float    g_fnj[(size_t)NN * HFC];   // nfeats @ W_nj
__device__ float    g_h  [(size_t)NN * HFC];   // nfeats @ W_node + b
__device__ float    g_ex [(size_t)EE * 4];     // logits, then exp(logit - max)
__device__ unsigned g_m  [(size_t)NN * 4];     // segment max (order-preserving uint)
__device__ float    g_s  [(size_t)NN * 4];     // segment sum
__device__ float2   g_wp [3 * 64 * HFC];       // k-pair-packed node weights

// order-preserving float<->uint transform for unsigned atomicMax
__device__ __forceinline__ unsigned ford(float f) {
    unsigned b = __float_as_uint(f);
    return (b & 0x80000000u) ? ~b : (b | 0x80000000u);
}
__device__ __forceinline__ float unford(unsigned u) {
    return __uint_as_float((u & 0x80000000u) ? (u & 0x7fffffffu) : ~u);
}

__device__ __forceinline__ void red_add_v4(float* p, float4 v) {
    asm volatile("red.global.add.v4.f32 [%0], {%1,%2,%3,%4};"
                 :: "l"(p), "f"(v.x), "f"(v.y), "f"(v.z), "f"(v.w) : "memory");
}

// packed fp32x2 FMA (2 MACs per issue slot on sm_103a)
__device__ __forceinline__ float2 ffma2(float2 a, float2 b, float2 c) {
    unsigned long long au, bu, cu, du;
    au = reinterpret_cast<unsigned long long&>(a);
    bu = reinterpret_cast<unsigned long long&>(b);
    cu = reinterpret_cast<unsigned long long&>(c);
    asm("fma.rn.f32x2 %0, %1, %2, %3;" : "=l"(du) : "l"(au), "l"(bu), "l"(cu));
    float2 d;
    reinterpret_cast<unsigned long long&>(d) = du;
    return d;
}

// ---------------------------------------------------------------------------
// 0) zero h_out, g_s, g_m; pack node weights into float2 k-pairs
// ---------------------------------------------------------------------------
__global__ void setup_kernel(float* __restrict__ hout,
                             const float* __restrict__ Wni,
                             const float* __restrict__ Wnj,
                             const float* __restrict__ Wn, int N)
{
    int stride = gridDim.x * blockDim.x;
    int i = blockIdx.x * blockDim.x + threadIdx.x;
    int n4 = N * 4;
    for (int j = i; j < n4; j += stride) { g_m[j] = 0u; g_s[j] = 0.0f; }
    int nh = N * HFC;
    for (int j = i; j < nh; j += stride) hout[j] = 0.0f;
    // pack: g_wp[m][k2][c] = (W[2k2][c], W[2k2+1][c])
    for (int j = i; j < 3 * 64 * HFC; j += stride) {
        int m = j / (64 * HFC);
        int r = j - m * (64 * HFC);
        int k2 = r / HFC, c = r - k2 * HFC;
        const float* W = (m == 0) ? Wni : (m == 1) ? Wnj : Wn;
        g_wp[j] = make_float2(W[(2 * k2) * HFC + c], W[(2 * k2 + 1) * HFC + c]);
    }
}

// ---------------------------------------------------------------------------
// 1) node projections: f_ni, f_nj, h  (three 128x128 GEMMs fused)
//    128 threads (one output column each), 64 nodes per block, FFMA2 inner
// ---------------------------------------------------------------------------
__global__ __launch_bounds__(128) void node_proj(
    const float* __restrict__ x, const float* __restrict__ bn, int N)
{
    __shared__ float xs[64 * IN_N];          // 32 KB, row-major
    const int c = threadIdx.x;
    const int base = blockIdx.x * 64;
    const int nrows = min(64, N - base);

    {   // stage node tile (coalesced, conflict-free)
        const float4* xg = (const float4*)(x + (size_t)base * IN_N);
        float4* xs4 = (float4*)xs;
        int tot4 = nrows * (IN_N / 4);
        for (int i = c; i < tot4; i += 128) xs4[i] = xg[i];
    }
    __syncthreads();

    const float bias_n = bn[c];

    for (int m = 0; m < 3; m++) {
        const float2* Wp = g_wp + m * (64 * HFC);
        float* O   = (m == 0) ? g_fni : (m == 1) ? g_fnj : g_h;
        float bias = (m == 2) ? bias_n : 0.0f;

        for (int g = 0; g < 64; g += 16) {
            if (g >= nrows) break;
            float2 acc[16];
            #pragma unroll
            for (int i = 0; i < 16; i++) acc[i] = make_float2(0.f, 0.f);

            #pragma unroll 4
            for (int k4 = 0; k4 < 32; k4++) {
                float2 wA = Wp[(2 * k4) * HFC + c];       // (W[4k4],W[4k4+1]) col c
                float2 wB = Wp[(2 * k4 + 1) * HFC + c];   // (W[4k4+2],W[4k4+3])
                #pragma unroll
                for (int i = 0; i < 16; i++) {
                    float4 xv = *(const float4*)&xs[(g + i) * IN_N + 4 * k4];
                    acc[i] = ffma2(make_float2(xv.x, xv.y), wA, acc[i]);
                    acc[i] = ffma2(make_float2(xv.z, xv.w), wB, acc[i]);
                }
            }
            int gn = min(16, nrows - g);
            for (int i = 0; i < gn; i++)
                O[(size_t)(base + g + i) * HFC + c] = acc[i].x + acc[i].y + bias;
        }
    }
}

// ---------------------------------------------------------------------------
// 2) per-edge: f_out = lrelu(f_ni[src] + f_nj[dst] + efeats@W_fij + bias),
//    write f_out (streaming), logits, atomicMax per (dst, head)
//    W_fij column k-pair-packed in registers; gathers issued ahead of GEMM
// ---------------------------------------------------------------------------
#define EPB1 8
__global__ __launch_bounds__(128) void edge_pass1(
    const float* __restrict__ ef, const int* __restrict__ src,
    const int* __restrict__ dst, const float* __restrict__ Wf,
    const float* __restrict__ attn, const float* __restrict__ bias,
    float* __restrict__ fout, int E)
{
    const int c = threadIdx.x;
    const int head = c >> 5;
    const int lane = c & 31;

    float2 wc2[IN_E / 2];
    #pragma unroll
    for (int k2 = 0; k2 < IN_E / 2; k2++)
        wc2[k2] = make_float2(Wf[(2 * k2) * HFC + c], Wf[(2 * k2 + 1) * HFC + c]);
    const float av = attn[head * 32 + lane];
    const float bv = bias[c];

    __shared__ float efs[EPB1][IN_E];
    __shared__ int sidx[EPB1], didx[EPB1];

    for (long long e0 = (long long)blockIdx.x * EPB1; e0 < E;
         e0 += (long long)gridDim.x * EPB1) {
        int ne = min(EPB1, (int)(E - e0));
        __syncthreads();
        if (c < ne)                    sidx[c] = src[e0 + c];
        else if (c >= 32 && c < 32 + ne) didx[c - 32] = dst[e0 + (c - 32)];
        {   // stage edge-feature rows, streaming reads (read-once data)
            int tot = ne * (IN_E / 4);
            const float4* eg = (const float4*)(ef + (size_t)e0 * IN_E);
            for (int i = c; i < tot; i += 128)
                ((float4*)efs)[i] = __ldcs(eg + i);
        }
        __syncthreads();

        // issue all gathers up-front (MLP ~16, overlaps the GEMM below)
        float fv[EPB1], gv[EPB1];
        #pragma unroll
        for (int j = 0; j < EPB1; j++) {
            if (j < ne) {
                fv[j] = __ldg(&g_fni[(size_t)sidx[j] * HFC + c]);
                gv[j] = __ldg(&g_fnj[(size_t)didx[j] * HFC + c]);
            }
        }

        float2 acc[EPB1];
        #pragma unroll
        for (int j = 0; j < EPB1; j++) acc[j] = make_float2(0.f, 0.f);

        #pragma unroll 4
        for (int k4 = 0; k4 < IN_E / 4; k4++) {
            #pragma unroll
            for (int j = 0; j < EPB1; j++) {
                float4 xv = *(const float4*)&efs[j][4 * k4];
                acc[j] = ffma2(make_float2(xv.x, xv.y), wc2[2 * k4], acc[j]);
                acc[j] = ffma2(make_float2(xv.z, xv.w), wc2[2 * k4 + 1], acc[j]);
            }
        }

        #pragma unroll
        for (int j = 0; j < EPB1; j++) {
            if (j >= ne) break;
            long long e = e0 + j;
            float v = acc[j].x + acc[j].y + bv + fv[j] + gv[j];
            v = (v > 0.0f) ? v : 0.01f * v;               // leaky relu
            __stcs(&fout[(size_t)e * HFC + c], v);        // write-once: stream
            float t = v * av;                             // attn logit
            #pragma unroll
            for (int o = 16; o > 0; o >>= 1)
                t += __shfl_xor_sync(0xffffffffu, t, o);
            if (lane == 0) {
                g_ex[e * 4 + head] = t;
                atomicMax(&g_m[(size_t)didx[j] * 4 + head], ford(t));
            }
        }
    }
}

// ---------------------------------------------------------------------------
// 3) ex = exp(e - m[dst]); segment sum
// ---------------------------------------------------------------------------
__global__ void pass2(const int* __restrict__ dst, int E) {
    int i = blockIdx.x * blockDim.x + threadIdx.x;
    int tot = E * 4;
    if (i >= tot) return;
    int e = i >> 2, h = i & 3;
    int d = dst[e];
    float m = unford(g_m[(size_t)d * 4 + h]);
    float ex = __expf(g_ex[i] - m);
    g_ex[i] = ex;
    atomicAdd(&g_s[(size_t)d * 4 + h], ex);
}

// ---------------------------------------------------------------------------
// 4) a = ex/s[dst]; h_out[dst] += h[src]*a  (vector RED, warp per edge)
// ---------------------------------------------------------------------------
#define EPB3 8
__global__ __launch_bounds__(128) void pass3(
    const int* __restrict__ src, const int* __restrict__ dst,
    float* __restrict__ hout, int E)
{
    const int warp = threadIdx.x >> 5;
    const int lane = threadIdx.x & 31;
    const int head = lane >> 3;                 // lane*4 feats -> head = lane/8
    long long base = (long long)blockIdx.x * EPB3;
    #pragma unroll
    for (int r = 0; r < EPB3 / 4; r++) {
        long long e = base + r * 4 + warp;
        if (e >= E) return;
        int s = src[e], d = dst[e];
        float ex = __ldcs(&g_ex[e * 4 + head]);           // read-once: stream
        float a = __fdividef(ex, g_s[(size_t)d * 4 + head]);
        float4 hv = ((const float4*)(g_h + (size_t)s * HFC))[lane];
        float4 v = make_float4(hv.x * a, hv.y * a, hv.z * a, hv.w * a);
        red_add_v4(hout + (size_t)d * HFC + lane * 4, v);
    }
}

// ---------------------------------------------------------------------------
extern "C" void kernel_launch(void* const* d_in, const int* in_sizes, int n_in,
                              void* d_out, int out_size)
{
    const float* nfeats = (const float*)d_in[0];
    const float* efeats = (const float*)d_in[1];
    const int*   src    = (const int*)d_in[2];
    const int*   dst    = (const int*)d_in[3];
    const float* W_node = (const float*)d_in[4];
    const float* b_node = (const float*)d_in[5];
    const float* W_ni   = (const float*)d_in[6];
    const float* W_nj   = (const float*)d_in[7];
    const float* W_fij  = (const float*)d_in[8];
    const float* attn   = (const float*)d_in[9];
    const float* bias   = (const float*)d_in[10];

    const int N = in_sizes[0] / IN_N;   // 100000
    const int E = in_sizes[2];          // 1000000

    float* h_out = (float*)d_out;                       // [N, 128]
    float* f_out = (float*)d_out + (size_t)N * HFC;     // [E, 128]

    setup_kernel<<<1024, 256>>>(h_out, W_ni, W_nj, W_node, N);

    node_proj<<<(N + 63) / 64, 128>>>(nfeats, b_node, N);

    edge_pass1<<<148 * 8, 128>>>(efeats, src, dst, W_fij, attn, bias, f_out, E);

    pass2<<<(E * 4 + 255) / 256, 256>>>(dst, E);

    pass3<<<(E + EPB3 - 1) / EPB3, 128>>>(src, dst, h_out, E);
}

// round 9
// speedup vs baseline: 1.3776x; 1.0223x over previous
#include <cuda_runtime.h>
#include <cuda_bf16.h>

#define NN 100000
#define EE 1000000
#define IN_N 128
#define IN_E 64
#define HFC 128   // H*F = 4*32 = 128 for both node and edge projections

// ---- scratch (static device allocations are the allowed mechanism) ----
__device__ float    g_fni[(size_t)NN * HFC];   // nfeats @ W_ni
__device__ float    g_fnj[(size_t)NN * HFC];   // nfeats @ W_nj
__device__ float    g_h  [(size_t)NN * HFC];   // nfeats @ W_node + b
__device__ float    g_ex [(size_t)EE * 4];     // logits, then exp(logit - max)
__device__ unsigned g_m  [(size_t)NN * 4];     // segment max (order-preserving uint)
__device__ float    g_s  [(size_t)NN * 4];     // segment sum
__device__ float2   g_wp [3 * 64 * HFC];       // k-pair-packed node weights

// order-preserving float<->uint transform for unsigned atomicMax
__device__ __forceinline__ unsigned ford(float f) {
    unsigned b = __float_as_uint(f);
    return (b & 0x80000000u) ? ~b : (b | 0x80000000u);
}
__device__ __forceinline__ float unford(unsigned u) {
    return __uint_as_float((u & 0x80000000u) ? (u & 0x7fffffffu) : ~u);
}

__device__ __forceinline__ void red_add_v4(float* p, float4 v) {
    asm volatile("red.global.add.v4.f32 [%0], {%1,%2,%3,%4};"
                 :: "l"(p), "f"(v.x), "f"(v.y), "f"(v.z), "f"(v.w) : "memory");
}

// packed fp32x2 FMA (2 MACs per issue slot on sm_103a)
__device__ __forceinline__ float2 ffma2(float2 a, float2 b, float2 c) {
    unsigned long long au, bu, cu, du;
    au = reinterpret_cast<unsigned long long&>(a);
    bu = reinterpret_cast<unsigned long long&>(b);
    cu = reinterpret_cast<unsigned long long&>(c);
    asm("fma.rn.f32x2 %0, %1, %2, %3;" : "=l"(du) : "l"(au), "l"(bu), "l"(cu));
    float2 d;
    reinterpret_cast<unsigned long long&>(d) = du;
    return d;
}

// ---------------------------------------------------------------------------
// 0) zero h_out, g_s, g_m; pack node weights into float2 k-pairs
// ---------------------------------------------------------------------------
__global__ void setup_kernel(float* __restrict__ hout,
                             const float* __restrict__ Wni,
                             const float* __restrict__ Wnj,
                             const float* __restrict__ Wn, int N)
{
    int stride = gridDim.x * blockDim.x;
    int i = blockIdx.x * blockDim.x + threadIdx.x;
    int n4 = N * 4;
    for (int j = i; j < n4; j += stride) { g_m[j] = 0u; g_s[j] = 0.0f; }
    int nh = N * HFC;
    for (int j = i; j < nh; j += stride) hout[j] = 0.0f;
    // pack: g_wp[m][k2][c] = (W[2k2][c], W[2k2+1][c])
    for (int j = i; j < 3 * 64 * HFC; j += stride) {
        int m = j / (64 * HFC);
        int r = j - m * (64 * HFC);
        int k2 = r / HFC, c = r - k2 * HFC;
        const float* W = (m == 0) ? Wni : (m == 1) ? Wnj : Wn;
        g_wp[j] = make_float2(W[(2 * k2) * HFC + c], W[(2 * k2 + 1) * HFC + c]);
    }
}

// ---------------------------------------------------------------------------
// 1) node projections: f_ni, f_nj, h  (three 128x128 GEMMs fused)
//    128 threads; each thread owns 2 output columns (c2, c2+64) and one
//    32-row half; FFMA2 inner, 4:1 FFMA2:LDS issue ratio
// ---------------------------------------------------------------------------
__global__ __launch_bounds__(128) void node_proj(
    const float* __restrict__ x, const float* __restrict__ bn, int N)
{
    __shared__ float xs[64 * IN_N];          // 32 KB, row-major
    const int tid  = threadIdx.x;
    const int half = tid >> 6;               // 0/1 -> rows [0,32) / [32,64)
    const int c2   = tid & 63;               // columns c2 and c2+64
    const int base = blockIdx.x * 64;
    const int nrows = min(64, N - base);

    {   // stage node tile (coalesced, conflict-free)
        const float4* xg = (const float4*)(x + (size_t)base * IN_N);
        float4* xs4 = (float4*)xs;
        int tot4 = nrows * (IN_N / 4);
        for (int i = tid; i < tot4; i += 128) xs4[i] = xg[i];
    }
    __syncthreads();

    const float bias0 = bn[c2];
    const float bias1 = bn[c2 + 64];

    for (int m = 0; m < 3; m++) {
        const float2* Wp = g_wp + m * (64 * HFC);
        float* O   = (m == 0) ? g_fni : (m == 1) ? g_fnj : g_h;
        float b0 = (m == 2) ? bias0 : 0.0f;
        float b1 = (m == 2) ? bias1 : 0.0f;

        for (int g = 0; g < 32; g += 16) {
            int row0 = half * 32 + g;
            if (row0 >= nrows) break;
            float2 acc0[16], acc1[16];
            #pragma unroll
            for (int i = 0; i < 16; i++) {
                acc0[i] = make_float2(0.f, 0.f);
                acc1[i] = make_float2(0.f, 0.f);
            }

            #pragma unroll 4
            for (int k4 = 0; k4 < 32; k4++) {
                float2 wA0 = Wp[(2 * k4) * HFC + c2];
                float2 wB0 = Wp[(2 * k4 + 1) * HFC + c2];
                float2 wA1 = Wp[(2 * k4) * HFC + c2 + 64];
                float2 wB1 = Wp[(2 * k4 + 1) * HFC + c2 + 64];
                #pragma unroll
                for (int i = 0; i < 16; i++) {
                    float4 xv = *(const float4*)&xs[(row0 + i) * IN_N + 4 * k4];
                    float2 lo = make_float2(xv.x, xv.y);
                    float2 hi = make_float2(xv.z, xv.w);
                    acc0[i] = ffma2(lo, wA0, acc0[i]);
                    acc0[i] = ffma2(hi, wB0, acc0[i]);
                    acc1[i] = ffma2(lo, wA1, acc1[i]);
                    acc1[i] = ffma2(hi, wB1, acc1[i]);
                }
            }
            int gn = min(16, nrows - row0);
            for (int i = 0; i < gn; i++) {
                size_t ro = (size_t)(base + row0 + i) * HFC;
                O[ro + c2]      = acc0[i].x + acc0[i].y + b0;
                O[ro + c2 + 64] = acc1[i].x + acc1[i].y + b1;
            }
        }
    }
}

// ---------------------------------------------------------------------------
// 2) per-edge: f_out = lrelu(f_ni[src] + f_nj[dst] + efeats@W_fij + bias),
//    write f_out (streaming), logits, atomicMax per (dst, head)
//    FULL-TILE specialization (E multiple of EPB1 handled here; remainder by
//    edge_rem). Shuffle reductions interleaved across the 8 edges.
// ---------------------------------------------------------------------------
#define EPB1 8
__global__ __launch_bounds__(128) void edge_pass1(
    const float* __restrict__ ef, const int* __restrict__ src,
    const int* __restrict__ dst, const float* __restrict__ Wf,
    const float* __restrict__ attn, const float* __restrict__ bias,
    float* __restrict__ fout, int nTiles)
{
    const int c = threadIdx.x;
    const int head = c >> 5;
    const int lane = c & 31;

    float2 wc2[IN_E / 2];
    #pragma unroll
    for (int k2 = 0; k2 < IN_E / 2; k2++)
        wc2[k2] = make_float2(Wf[(2 * k2) * HFC + c], Wf[(2 * k2 + 1) * HFC + c]);
    const float av = attn[head * 32 + lane];
    const float bv = bias[c];

    __shared__ float efs[EPB1][IN_E];
    __shared__ int sidx[EPB1], didx[EPB1];

    for (long long tile = blockIdx.x; tile < nTiles; tile += gridDim.x) {
        long long e0 = tile * EPB1;
        __syncthreads();
        if (c < EPB1)                         sidx[c] = src[e0 + c];
        else if (c >= 32 && c < 32 + EPB1)    didx[c - 32] = dst[e0 + (c - 32)];
        {   // stage edge-feature rows, streaming reads (read-once data)
            const float4* eg = (const float4*)(ef + (size_t)e0 * IN_E);
            for (int i = c; i < EPB1 * (IN_E / 4); i += 128)
                ((float4*)efs)[i] = __ldcs(eg + i);
        }
        __syncthreads();

        // issue all gathers up-front (MLP 16, overlaps the GEMM below)
        float fv[EPB1], gv[EPB1];
        #pragma unroll
        for (int j = 0; j < EPB1; j++) {
            fv[j] = __ldg(&g_fni[(size_t)sidx[j] * HFC + c]);
            gv[j] = __ldg(&g_fnj[(size_t)didx[j] * HFC + c]);
        }

        float2 acc[EPB1];
        #pragma unroll
        for (int j = 0; j < EPB1; j++) acc[j] = make_float2(0.f, 0.f);

        #pragma unroll 4
        for (int k4 = 0; k4 < IN_E / 4; k4++) {
            #pragma unroll
            for (int j = 0; j < EPB1; j++) {
                float4 xv = *(const float4*)&efs[j][4 * k4];
                acc[j] = ffma2(make_float2(xv.x, xv.y), wc2[2 * k4], acc[j]);
                acc[j] = ffma2(make_float2(xv.z, xv.w), wc2[2 * k4 + 1], acc[j]);
            }
        }

        // tail: compute + store all v, then interleaved shuffle reductions
        float t[EPB1];
        #pragma unroll
        for (int j = 0; j < EPB1; j++) {
            float v = acc[j].x + acc[j].y + bv + fv[j] + gv[j];
            v = (v > 0.0f) ? v : 0.01f * v;               // leaky relu
            __stcs(&fout[(size_t)(e0 + j) * HFC + c], v); // write-once: stream
            t[j] = v * av;
        }
        #pragma unroll
        for (int o = 16; o > 0; o >>= 1) {
            #pragma unroll
            for (int j = 0; j < EPB1; j++)
                t[j] += __shfl_xor_sync(0xffffffffu, t[j], o);
        }
        if (lane == 0) {
            #pragma unroll
            for (int j = 0; j < EPB1; j++) {
                g_ex[(e0 + j) * 4 + head] = t[j];
                atomicMax(&g_m[(size_t)didx[j] * 4 + head], ford(t[j]));
            }
        }
    }
}

// remainder edges (E % EPB1), one small block; rarely used
__global__ __launch_bounds__(128) void edge_rem(
    const float* __restrict__ ef, const int* __restrict__ src,
    const int* __restrict__ dst, const float* __restrict__ Wf,
    const float* __restrict__ attn, const float* __restrict__ bias,
    float* __restrict__ fout, int e_begin, int E)
{
    const int c = threadIdx.x;
    const int head = c >> 5;
    const int lane = c & 31;
    const float av = attn[head * 32 + lane];
    for (int e = e_begin; e < E; e++) {
        int s = src[e], d = dst[e];
        float acc = bias[c];
        for (int k = 0; k < IN_E; k++)
            acc = fmaf(ef[(size_t)e * IN_E + k], Wf[k * HFC + c], acc);
        float v = acc + g_fni[(size_t)s * HFC + c] + g_fnj[(size_t)d * HFC + c];
        v = (v > 0.0f) ? v : 0.01f * v;
        fout[(size_t)e * HFC + c] = v;
        float t = v * av;
        #pragma unroll
        for (int o = 16; o > 0; o >>= 1)
            t += __shfl_xor_sync(0xffffffffu, t, o);
        if (lane == 0) {
            g_ex[(size_t)e * 4 + head] = t;
            atomicMax(&g_m[(size_t)d * 4 + head], ford(t));
        }
    }
}

// ---------------------------------------------------------------------------
// 3) ex = exp(e - m[dst]); segment sum
// ---------------------------------------------------------------------------
__global__ void pass2(const int* __restrict__ dst, int E) {
    int i = blockIdx.x * blockDim.x + threadIdx.x;
    int tot = E * 4;
    if (i >= tot) return;
    int e = i >> 2, h = i & 3;
    int d = dst[e];
    float m = unford(g_m[(size_t)d * 4 + h]);
    float ex = __expf(g_ex[i] - m);
    g_ex[i] = ex;
    atomicAdd(&g_s[(size_t)d * 4 + h], ex);
}

// ---------------------------------------------------------------------------
// 4) a = ex/s[dst]; h_out[dst] += h[src]*a  (vector RED, warp per edge)
//    4 edges per warp, batched loads -> batched gathers -> batched REDs
// ---------------------------------------------------------------------------
#define EPB3 16
__global__ __launch_bounds__(128) void pass3(
    const int* __restrict__ src, const int* __restrict__ dst,
    float* __restrict__ hout, int E)
{
    const int warp = threadIdx.x >> 5;
    const int lane = threadIdx.x & 31;
    const int head = lane >> 3;                 // lane*4 feats -> head = lane/8
    long long base = (long long)blockIdx.x * EPB3 + warp * (EPB3 / 4);

    int  s[4], d[4];
    float a[4];
    bool ok[4];
    #pragma unroll
    for (int r = 0; r < 4; r++) {
        long long e = base + r;
        ok[r] = (e < E);
        if (ok[r]) {
            s[r] = src[e]; d[r] = dst[e];
            float ex = __ldcs(&g_ex[e * 4 + head]);
            a[r] = __fdividef(ex, g_s[(size_t)d[r] * 4 + head]);
        }
    }
    float4 hv[4];
    #pragma unroll
    for (int r = 0; r < 4; r++)
        if (ok[r]) hv[r] = ((const float4*)(g_h + (size_t)s[r] * HFC))[lane];
    #pragma unroll
    for (int r = 0; r < 4; r++) {
        if (ok[r]) {
            float4 v = make_float4(hv[r].x * a[r], hv[r].y * a[r],
                                   hv[r].z * a[r], hv[r].w * a[r]);
            red_add_v4(hout + (size_t)d[r] * HFC + lane * 4, v);
        }
    }
}

// ---------------------------------------------------------------------------
extern "C" void kernel_launch(void* const* d_in, const int* in_sizes, int n_in,
                              void* d_out, int out_size)
{
    const float* nfeats = (const float*)d_in[0];
    const float* efeats = (const float*)d_in[1];
    const int*   src    = (const int*)d_in[2];
    const int*   dst    = (const int*)d_in[3];
    const float* W_node = (const float*)d_in[4];
    const float* b_node = (const float*)d_in[5];
    const float* W_ni   = (const float*)d_in[6];
    const float* W_nj   = (const float*)d_in[7];
    const float* W_fij  = (const float*)d_in[8];
    const float* attn   = (const float*)d_in[9];
    const float* bias   = (const float*)d_in[10];

    const int N = in_sizes[0] / IN_N;   // 100000
    const int E = in_sizes[2];          // 1000000

    float* h_out = (float*)d_out;                       // [N, 128]
    float* f_out = (float*)d_out + (size_t)N * HFC;     // [E, 128]

    setup_kernel<<<1024, 256>>>(h_out, W_ni, W_nj, W_node, N);

    node_proj<<<(N + 63) / 64, 128>>>(nfeats, b_node, N);

    int nTiles = E / EPB1;
    if (nTiles > 0)
        edge_pass1<<<148 * 8, 128>>>(efeats, src, dst, W_fij, attn, bias,
                                     f_out, nTiles);
    if (E % EPB1)
        edge_rem<<<1, 128>>>(efeats, src, dst, W_fij, attn, bias,
                             f_out, nTiles * EPB1, E);

    pass2<<<(E * 4 + 255) / 256, 256>>>(dst, E);

    pass3<<<(E + EPB3 - 1) / EPB3, 128>>>(src, dst, h_out, E);
}

// round 10
// speedup vs baseline: 1.3803x; 1.0020x over previous
#include <cuda_runtime.h>
#include <cuda_bf16.h>

#define NN 100000
#define EE 1000000
#define IN_N 128
#define IN_E 64
#define HFC 128   // H*F = 4*32 = 128 for both node and edge projections

// ---- scratch (static device allocations are the allowed mechanism) ----
__device__ float    g_fni[(size_t)NN * HFC];   // nfeats @ W_ni
__device__ float    g_fnj[(size_t)NN * HFC];   // nfeats @ W_nj
__device__ float    g_h  [(size_t)NN * HFC];   // nfeats @ W_node + b
__device__ float    g_ex [(size_t)EE * 4];     // raw attention logits [E,4]
__device__ float2   g_wp [3 * 64 * HFC];       // k-pair-packed node weights
// CSR over dst
__device__ int      g_cnt   [NN];              // counts, then scatter cursor
__device__ int      g_rowptr[NN + 1];
__device__ int      g_bsum  [512];
__device__ int      g_cidx  [EE];

__device__ __forceinline__ void red_add_v4(float* p, float4 v) {
    asm volatile("red.global.add.v4.f32 [%0], {%1,%2,%3,%4};"
                 :: "l"(p), "f"(v.x), "f"(v.y), "f"(v.z), "f"(v.w) : "memory");
}

// packed fp32x2 FMA (2 MACs per issue slot on sm_103a)
__device__ __forceinline__ float2 ffma2(float2 a, float2 b, float2 c) {
    unsigned long long au, bu, cu, du;
    au = reinterpret_cast<unsigned long long&>(a);
    bu = reinterpret_cast<unsigned long long&>(b);
    cu = reinterpret_cast<unsigned long long&>(c);
    asm("fma.rn.f32x2 %0, %1, %2, %3;" : "=l"(du) : "l"(au), "l"(bu), "l"(cu));
    float2 d;
    reinterpret_cast<unsigned long long&>(d) = du;
    return d;
}

__device__ __forceinline__ float compsel(float4 v, int h) {
    return (h == 0) ? v.x : (h == 1) ? v.y : (h == 2) ? v.z : v.w;
}

// ---------------------------------------------------------------------------
// 0) zero CSR counts; pack node weights into float2 k-pairs
// ---------------------------------------------------------------------------
__global__ void setup_kernel(const float* __restrict__ Wni,
                             const float* __restrict__ Wnj,
                             const float* __restrict__ Wn, int N)
{
    int stride = gridDim.x * blockDim.x;
    int i = blockIdx.x * blockDim.x + threadIdx.x;
    for (int j = i; j < N; j += stride) g_cnt[j] = 0;
    // pack: g_wp[m][k2][c] = (W[2k2][c], W[2k2+1][c])
    for (int j = i; j < 3 * 64 * HFC; j += stride) {
        int m = j / (64 * HFC);
        int r = j - m * (64 * HFC);
        int k2 = r / HFC, c = r - k2 * HFC;
        const float* W = (m == 0) ? Wni : (m == 1) ? Wnj : Wn;
        g_wp[j] = make_float2(W[(2 * k2) * HFC + c], W[(2 * k2 + 1) * HFC + c]);
    }
}

// ---- CSR build: count -> 2-level exclusive scan -> scatter -----------------
__global__ void csr_count(const int* __restrict__ dst, int E) {
    int e = blockIdx.x * blockDim.x + threadIdx.x;
    if (e < E) atomicAdd(&g_cnt[dst[e]], 1);
}

__global__ void scan_a(int N) {
    __shared__ int tmp[256];
    int t = threadIdx.x;
    int i = blockIdx.x * 256 + t;
    int v = (i < N) ? g_cnt[i] : 0;
    tmp[t] = v; __syncthreads();
    for (int off = 1; off < 256; off <<= 1) {
        int add = (t >= off) ? tmp[t - off] : 0;
        __syncthreads();
        tmp[t] += add;
        __syncthreads();
    }
    if (i < N) g_rowptr[i] = tmp[t] - v;          // exclusive within block
    if (t == 255) g_bsum[blockIdx.x] = tmp[255];  // block total
}

__global__ void scan_b(int nb) {
    __shared__ int tmp[512];
    int t = threadIdx.x;
    int v = (t < nb) ? g_bsum[t] : 0;
    tmp[t] = v; __syncthreads();
    for (int off = 1; off < 512; off <<= 1) {
        int add = (t >= off) ? tmp[t - off] : 0;
        __syncthreads();
        tmp[t] += add;
        __syncthreads();
    }
    g_bsum[t] = tmp[t] - v;                       // exclusive block offsets
}

__global__ void scan_c(int N, int E) {
    int i = blockIdx.x * 256 + threadIdx.x;
    if (i < N) {
        int r = g_rowptr[i] + g_bsum[blockIdx.x];
        g_rowptr[i] = r;
        g_cnt[i] = r;                              // scatter cursor
    }
    if (i == 0) g_rowptr[N] = E;
}

__global__ void csr_scatter(const int* __restrict__ dst, int E) {
    int e = blockIdx.x * blockDim.x + threadIdx.x;
    if (e < E) {
        int p = atomicAdd(&g_cnt[dst[e]], 1);
        g_cidx[p] = e;
    }
}

// ---------------------------------------------------------------------------
// 1) node projections: f_ni, f_nj, h  (three 128x128 GEMMs fused)
//    128 threads; each thread owns 2 output columns and one 32-row half
// ---------------------------------------------------------------------------
__global__ __launch_bounds__(128) void node_proj(
    const float* __restrict__ x, const float* __restrict__ bn, int N)
{
    __shared__ float xs[64 * IN_N];          // 32 KB, row-major
    const int tid  = threadIdx.x;
    const int half = tid >> 6;               // 0/1 -> rows [0,32) / [32,64)
    const int c2   = tid & 63;               // columns c2 and c2+64
    const int base = blockIdx.x * 64;
    const int nrows = min(64, N - base);

    {   // stage node tile (coalesced, conflict-free)
        const float4* xg = (const float4*)(x + (size_t)base * IN_N);
        float4* xs4 = (float4*)xs;
        int tot4 = nrows * (IN_N / 4);
        for (int i = tid; i < tot4; i += 128) xs4[i] = xg[i];
    }
    __syncthreads();

    const float bias0 = bn[c2];
    const float bias1 = bn[c2 + 64];

    for (int m = 0; m < 3; m++) {
        const float2* Wp = g_wp + m * (64 * HFC);
        float* O   = (m == 0) ? g_fni : (m == 1) ? g_fnj : g_h;
        float b0 = (m == 2) ? bias0 : 0.0f;
        float b1 = (m == 2) ? bias1 : 0.0f;

        for (int g = 0; g < 32; g += 16) {
            int row0 = half * 32 + g;
            if (row0 >= nrows) break;
            float2 acc0[16], acc1[16];
            #pragma unroll
            for (int i = 0; i < 16; i++) {
                acc0[i] = make_float2(0.f, 0.f);
                acc1[i] = make_float2(0.f, 0.f);
            }

            #pragma unroll 4
            for (int k4 = 0; k4 < 32; k4++) {
                float2 wA0 = Wp[(2 * k4) * HFC + c2];
                float2 wB0 = Wp[(2 * k4 + 1) * HFC + c2];
                float2 wA1 = Wp[(2 * k4) * HFC + c2 + 64];
                float2 wB1 = Wp[(2 * k4 + 1) * HFC + c2 + 64];
                #pragma unroll
                for (int i = 0; i < 16; i++) {
                    float4 xv = *(const float4*)&xs[(row0 + i) * IN_N + 4 * k4];
                    float2 lo = make_float2(xv.x, xv.y);
                    float2 hi = make_float2(xv.z, xv.w);
                    acc0[i] = ffma2(lo, wA0, acc0[i]);
                    acc0[i] = ffma2(hi, wB0, acc0[i]);
                    acc1[i] = ffma2(lo, wA1, acc1[i]);
                    acc1[i] = ffma2(hi, wB1, acc1[i]);
                }
            }
            int gn = min(16, nrows - row0);
            for (int i = 0; i < gn; i++) {
                size_t ro = (size_t)(base + row0 + i) * HFC;
                O[ro + c2]      = acc0[i].x + acc0[i].y + b0;
                O[ro + c2 + 64] = acc1[i].x + acc1[i].y + b1;
            }
        }
    }
}

// ---------------------------------------------------------------------------
// 2) per-edge: f_out = lrelu(f_ni[src] + f_nj[dst] + efeats@W_fij + bias),
//    write f_out (streaming), raw logits to g_ex. No atomics.
// ---------------------------------------------------------------------------
#define EPB1 8
__global__ __launch_bounds__(128) void edge_pass1(
    const float* __restrict__ ef, const int* __restrict__ src,
    const int* __restrict__ dst, const float* __restrict__ Wf,
    const float* __restrict__ attn, const float* __restrict__ bias,
    float* __restrict__ fout, int nTiles)
{
    const int c = threadIdx.x;
    const int head = c >> 5;
    const int lane = c & 31;

    float2 wc2[IN_E / 2];
    #pragma unroll
    for (int k2 = 0; k2 < IN_E / 2; k2++)
        wc2[k2] = make_float2(Wf[(2 * k2) * HFC + c], Wf[(2 * k2 + 1) * HFC + c]);
    const float av = attn[head * 32 + lane];
    const float bv = bias[c];

    __shared__ float efs[EPB1][IN_E];
    __shared__ int sidx[EPB1], didx[EPB1];

    for (long long tile = blockIdx.x; tile < nTiles; tile += gridDim.x) {
        long long e0 = tile * EPB1;
        __syncthreads();
        if (c < EPB1)                         sidx[c] = src[e0 + c];
        else if (c >= 32 && c < 32 + EPB1)    didx[c - 32] = dst[e0 + (c - 32)];
        {   // stage edge-feature rows, streaming reads (read-once data)
            const float4* eg = (const float4*)(ef + (size_t)e0 * IN_E);
            for (int i = c; i < EPB1 * (IN_E / 4); i += 128)
                ((float4*)efs)[i] = __ldcs(eg + i);
        }
        __syncthreads();

        // issue all gathers up-front (MLP 16, overlaps the GEMM below)
        float fv[EPB1], gv[EPB1];
        #pragma unroll
        for (int j = 0; j < EPB1; j++) {
            fv[j] = __ldg(&g_fni[(size_t)sidx[j] * HFC + c]);
            gv[j] = __ldg(&g_fnj[(size_t)didx[j] * HFC + c]);
        }

        float2 acc[EPB1];
        #pragma unroll
        for (int j = 0; j < EPB1; j++) acc[j] = make_float2(0.f, 0.f);

        #pragma unroll 4
        for (int k4 = 0; k4 < IN_E / 4; k4++) {
            #pragma unroll
            for (int j = 0; j < EPB1; j++) {
                float4 xv = *(const float4*)&efs[j][4 * k4];
                acc[j] = ffma2(make_float2(xv.x, xv.y), wc2[2 * k4], acc[j]);
                acc[j] = ffma2(make_float2(xv.z, xv.w), wc2[2 * k4 + 1], acc[j]);
            }
        }

        // tail: compute + store all v, then interleaved shuffle reductions
        float t[EPB1];
        #pragma unroll
        for (int j = 0; j < EPB1; j++) {
            float v = acc[j].x + acc[j].y + bv + fv[j] + gv[j];
            v = (v > 0.0f) ? v : 0.01f * v;               // leaky relu
            __stcs(&fout[(size_t)(e0 + j) * HFC + c], v); // write-once: stream
            t[j] = v * av;
        }
        #pragma unroll
        for (int o = 16; o > 0; o >>= 1) {
            #pragma unroll
            for (int j = 0; j < EPB1; j++)
                t[j] += __shfl_xor_sync(0xffffffffu, t[j], o);
        }
        if (lane == 0) {
            #pragma unroll
            for (int j = 0; j < EPB1; j++)
                g_ex[(e0 + j) * 4 + head] = t[j];
        }
    }
}

// remainder edges (E % EPB1); rarely used
__global__ __launch_bounds__(128) void edge_rem(
    const float* __restrict__ ef, const int* __restrict__ src,
    const int* __restrict__ dst, const float* __restrict__ Wf,
    const float* __restrict__ attn, const float* __restrict__ bias,
    float* __restrict__ fout, int e_begin, int E)
{
    const int c = threadIdx.x;
    const int head = c >> 5;
    const int lane = c & 31;
    const float av = attn[head * 32 + lane];
    for (int e = e_begin; e < E; e++) {
        int s = src[e], d = dst[e];
        float acc = bias[c];
        for (int k = 0; k < IN_E; k++)
            acc = fmaf(ef[(size_t)e * IN_E + k], Wf[k * HFC + c], acc);
        float v = acc + g_fni[(size_t)s * HFC + c] + g_fnj[(size_t)d * HFC + c];
        v = (v > 0.0f) ? v : 0.01f * v;
        fout[(size_t)e * HFC + c] = v;
        float t = v * av;
        #pragma unroll
        for (int o = 16; o > 0; o >>= 1)
            t += __shfl_xor_sync(0xffffffffu, t, o);
        if (lane == 0)
            g_ex[(size_t)e * 4 + head] = t;
    }
}

// ---------------------------------------------------------------------------
// 3) fused per-node softmax + aggregation. One warp per node, no atomics.
//    h_out[d] = sum_e softmax_e(logit) * h[src[e]]   (per head)
// ---------------------------------------------------------------------------
#define AGG_WARPS 8
#define AGG_CAP 128
__global__ __launch_bounds__(256) void agg(
    const int* __restrict__ src, float* __restrict__ hout, int N)
{
    __shared__ float sa[AGG_WARPS][AGG_CAP * 4];   // exp values per edge/head
    __shared__ int   ss[AGG_WARPS][AGG_CAP];       // src ids
    const int w = threadIdx.x >> 5;
    const int lane = threadIdx.x & 31;
    const int d = blockIdx.x * AGG_WARPS + w;
    if (d >= N) return;

    const int start = g_rowptr[d];
    const int deg = g_rowptr[d + 1] - start;
    const float NEG = __int_as_float(0xff800000);   // -inf

    // phase 1a: per-head max over incoming edges
    float4 m4 = make_float4(NEG, NEG, NEG, NEG);
    for (int t = lane; t < deg; t += 32) {
        int eid = g_cidx[start + t];
        float4 l4 = *(const float4*)&g_ex[(size_t)eid * 4];
        m4.x = fmaxf(m4.x, l4.x); m4.y = fmaxf(m4.y, l4.y);
        m4.z = fmaxf(m4.z, l4.z); m4.w = fmaxf(m4.w, l4.w);
    }
    #pragma unroll
    for (int o = 16; o > 0; o >>= 1) {
        m4.x = fmaxf(m4.x, __shfl_xor_sync(0xffffffffu, m4.x, o));
        m4.y = fmaxf(m4.y, __shfl_xor_sync(0xffffffffu, m4.y, o));
        m4.z = fmaxf(m4.z, __shfl_xor_sync(0xffffffffu, m4.z, o));
        m4.w = fmaxf(m4.w, __shfl_xor_sync(0xffffffffu, m4.w, o));
    }

    // phase 1b: exp + sum, stash exp values and src ids in SMEM
    float4 s4 = make_float4(0.f, 0.f, 0.f, 0.f);
    for (int t = lane; t < deg; t += 32) {
        int eid = g_cidx[start + t];
        float4 l4 = *(const float4*)&g_ex[(size_t)eid * 4];
        float4 e4 = make_float4(__expf(l4.x - m4.x), __expf(l4.y - m4.y),
                                __expf(l4.z - m4.z), __expf(l4.w - m4.w));
        s4.x += e4.x; s4.y += e4.y; s4.z += e4.z; s4.w += e4.w;
        if (t < AGG_CAP) {
            *(float4*)&sa[w][t * 4] = e4;
            ss[w][t] = src[eid];
        }
    }
    #pragma unroll
    for (int o = 16; o > 0; o >>= 1) {
        s4.x += __shfl_xor_sync(0xffffffffu, s4.x, o);
        s4.y += __shfl_xor_sync(0xffffffffu, s4.y, o);
        s4.z += __shfl_xor_sync(0xffffffffu, s4.z, o);
        s4.w += __shfl_xor_sync(0xffffffffu, s4.w, o);
    }
    __syncwarp();

    const int head = lane >> 3;
    const float inv = __fdividef(1.0f, compsel(s4, head));
    const float mh = compsel(m4, head);

    // phase 2: aggregate h[src]*a with MLP-4 grouped gathers
    float4 acc = make_float4(0.f, 0.f, 0.f, 0.f);
    for (int t0 = 0; t0 < deg; t0 += 4) {
        int n = min(4, deg - t0);
        float a[4]; int s[4];
        #pragma unroll
        for (int r = 0; r < 4; r++) {
            if (r < n) {
                int t = t0 + r;
                if (t < AGG_CAP) {
                    a[r] = sa[w][t * 4 + head] * inv;
                    s[r] = ss[w][t];
                } else {                           // overflow fallback (rare)
                    int eid = g_cidx[start + t];
                    float4 l4 = *(const float4*)&g_ex[(size_t)eid * 4];
                    a[r] = __expf(compsel(l4, head) - mh) * inv;
                    s[r] = src[eid];
                }
            }
        }
        float4 hv[4];
        #pragma unroll
        for (int r = 0; r < 4; r++)
            if (r < n) hv[r] = __ldg(&((const float4*)(g_h + (size_t)s[r] * HFC))[lane]);
        #pragma unroll
        for (int r = 0; r < 4; r++) {
            if (r < n) {
                acc.x = fmaf(hv[r].x, a[r], acc.x);
                acc.y = fmaf(hv[r].y, a[r], acc.y);
                acc.z = fmaf(hv[r].z, a[r], acc.z);
                acc.w = fmaf(hv[r].w, a[r], acc.w);
            }
        }
    }
    ((float4*)(hout + (size_t)d * HFC))[lane] = acc;
}

// ---------------------------------------------------------------------------
extern "C" void kernel_launch(void* const* d_in, const int* in_sizes, int n_in,
                              void* d_out, int out_size)
{
    const float* nfeats = (const float*)d_in[0];
    const float* efeats = (const float*)d_in[1];
    const int*   src    = (const int*)d_in[2];
    const int*   dst    = (const int*)d_in[3];
    const float* W_node = (const float*)d_in[4];
    const float* b_node = (const float*)d_in[5];
    const float* W_ni   = (const float*)d_in[6];
    const float* W_nj   = (const float*)d_in[7];
    const float* W_fij  = (const float*)d_in[8];
    const float* attn   = (const float*)d_in[9];
    const float* bias   = (const float*)d_in[10];

    const int N = in_sizes[0] / IN_N;   // 100000
    const int E = in_sizes[2];          // 1000000

    float* h_out = (float*)d_out;                       // [N, 128]
    float* f_out = (float*)d_out + (size_t)N * HFC;     // [E, 128]

    setup_kernel<<<512, 256>>>(W_ni, W_nj, W_node, N);

    // CSR build over dst
    int nb = (N + 255) / 256;
    csr_count  <<<(E + 255) / 256, 256>>>(dst, E);
    scan_a     <<<nb, 256>>>(N);
    scan_b     <<<1, 512>>>(nb);
    scan_c     <<<nb, 256>>>(N, E);
    csr_scatter<<<(E + 255) / 256, 256>>>(dst, E);

    node_proj<<<(N + 63) / 64, 128>>>(nfeats, b_node, N);

    int nTiles = E / EPB1;
    if (nTiles > 0)
        edge_pass1<<<148 * 8, 128>>>(efeats, src, dst, W_fij, attn, bias,
                                     f_out, nTiles);
    if (E % EPB1)
        edge_rem<<<1, 128>>>(efeats, src, dst, W_fij, attn, bias,
                             f_out, nTiles * EPB1, E);

    agg<<<(N + AGG_WARPS - 1) / AGG_WARPS, 256>>>(src, h_out, N);
}

// round 11
// speedup vs baseline: 1.4451x; 1.0470x over previous
#include <cuda_runtime.h>
#include <cuda_bf16.h>

#define NN 100000
#define EE 1000000
#define IN_N 128
#define IN_E 64
#define HFC 128   // H*F = 4*32 = 128 for both node and edge projections

// ---- scratch (static device allocations are the allowed mechanism) ----
__device__ float    g_fni[(size_t)NN * HFC];   // nfeats @ W_ni
__device__ float    g_fnj[(size_t)NN * HFC];   // nfeats @ W_nj
__device__ float    g_h  [(size_t)NN * HFC];   // nfeats @ W_node + b
__device__ float    g_ex [(size_t)EE * 4];     // raw attention logits [E,4]
__device__ float2   g_wp [3 * 64 * HFC];       // k-pair-packed node weights
// CSR over dst
__device__ int      g_cnt   [NN];              // counts, then scatter cursor
__device__ int      g_rowptr[NN + 1];
__device__ int      g_bsum  [512];
__device__ int      g_cidx  [EE];

// packed fp32x2 FMA (2 MACs per issue slot on sm_103a)
__device__ __forceinline__ float2 ffma2(float2 a, float2 b, float2 c) {
    unsigned long long au, bu, cu, du;
    au = reinterpret_cast<unsigned long long&>(a);
    bu = reinterpret_cast<unsigned long long&>(b);
    cu = reinterpret_cast<unsigned long long&>(c);
    asm("fma.rn.f32x2 %0, %1, %2, %3;" : "=l"(du) : "l"(au), "l"(bu), "l"(cu));
    float2 d;
    reinterpret_cast<unsigned long long&>(d) = du;
    return d;
}

__device__ __forceinline__ float compsel(float4 v, int h) {
    return (h == 0) ? v.x : (h == 1) ? v.y : (h == 2) ? v.z : v.w;
}

// ---------------------------------------------------------------------------
// 0) zero CSR counts; pack node weights into float2 k-pairs
// ---------------------------------------------------------------------------
__global__ void setup_kernel(const float* __restrict__ Wni,
                             const float* __restrict__ Wnj,
                             const float* __restrict__ Wn, int N)
{
    int stride = gridDim.x * blockDim.x;
    int i = blockIdx.x * blockDim.x + threadIdx.x;
    for (int j = i; j < N; j += stride) g_cnt[j] = 0;
    // pack: g_wp[m][k2][c] = (W[2k2][c], W[2k2+1][c])
    for (int j = i; j < 3 * 64 * HFC; j += stride) {
        int m = j / (64 * HFC);
        int r = j - m * (64 * HFC);
        int k2 = r / HFC, c = r - k2 * HFC;
        const float* W = (m == 0) ? Wni : (m == 1) ? Wnj : Wn;
        g_wp[j] = make_float2(W[(2 * k2) * HFC + c], W[(2 * k2 + 1) * HFC + c]);
    }
}

// ---- CSR build: count -> 2-level exclusive scan -> scatter -----------------
__global__ void csr_count(const int* __restrict__ dst, int E) {
    int e = blockIdx.x * blockDim.x + threadIdx.x;
    if (e < E) atomicAdd(&g_cnt[dst[e]], 1);
}

__global__ void scan_a(int N) {
    __shared__ int tmp[256];
    int t = threadIdx.x;
    int i = blockIdx.x * 256 + t;
    int v = (i < N) ? g_cnt[i] : 0;
    tmp[t] = v; __syncthreads();
    for (int off = 1; off < 256; off <<= 1) {
        int add = (t >= off) ? tmp[t - off] : 0;
        __syncthreads();
        tmp[t] += add;
        __syncthreads();
    }
    if (i < N) g_rowptr[i] = tmp[t] - v;          // exclusive within block
    if (t == 255) g_bsum[blockIdx.x] = tmp[255];  // block total
}

__global__ void scan_b(int nb) {
    __shared__ int tmp[512];
    int t = threadIdx.x;
    int v = (t < nb) ? g_bsum[t] : 0;
    tmp[t] = v; __syncthreads();
    for (int off = 1; off < 512; off <<= 1) {
        int add = (t >= off) ? tmp[t - off] : 0;
        __syncthreads();
        tmp[t] += add;
        __syncthreads();
    }
    g_bsum[t] = tmp[t] - v;                       // exclusive block offsets
}

__global__ void scan_c(int N, int E) {
    int i = blockIdx.x * 256 + threadIdx.x;
    if (i < N) {
        int r = g_rowptr[i] + g_bsum[blockIdx.x];
        g_rowptr[i] = r;
        g_cnt[i] = r;                              // scatter cursor
    }
    if (i == 0) g_rowptr[N] = E;
}

__global__ void csr_scatter(const int* __restrict__ dst, int E) {
    int e = blockIdx.x * blockDim.x + threadIdx.x;
    if (e < E) {
        int p = atomicAdd(&g_cnt[dst[e]], 1);
        g_cidx[p] = e;
    }
}

// ---------------------------------------------------------------------------
// 1) node projections: f_ni, f_nj, h  (three 128x128 GEMMs fused)
//    128 threads; each thread owns 2 output columns and one 32-row half
// ---------------------------------------------------------------------------
__global__ __launch_bounds__(128) void node_proj(
    const float* __restrict__ x, const float* __restrict__ bn, int N)
{
    __shared__ float xs[64 * IN_N];          // 32 KB, row-major
    const int tid  = threadIdx.x;
    const int half = tid >> 6;               // 0/1 -> rows [0,32) / [32,64)
    const int c2   = tid & 63;               // columns c2 and c2+64
    const int base = blockIdx.x * 64;
    const int nrows = min(64, N - base);

    {   // stage node tile (coalesced, conflict-free)
        const float4* xg = (const float4*)(x + (size_t)base * IN_N);
        float4* xs4 = (float4*)xs;
        int tot4 = nrows * (IN_N / 4);
        for (int i = tid; i < tot4; i += 128) xs4[i] = xg[i];
    }
    __syncthreads();

    const float bias0 = bn[c2];
    const float bias1 = bn[c2 + 64];

    for (int m = 0; m < 3; m++) {
        const float2* Wp = g_wp + m * (64 * HFC);
        float* O   = (m == 0) ? g_fni : (m == 1) ? g_fnj : g_h;
        float b0 = (m == 2) ? bias0 : 0.0f;
        float b1 = (m == 2) ? bias1 : 0.0f;

        for (int g = 0; g < 32; g += 16) {
            int row0 = half * 32 + g;
            if (row0 >= nrows) break;
            float2 acc0[16], acc1[16];
            #pragma unroll
            for (int i = 0; i < 16; i++) {
                acc0[i] = make_float2(0.f, 0.f);
                acc1[i] = make_float2(0.f, 0.f);
            }

            #pragma unroll 4
            for (int k4 = 0; k4 < 32; k4++) {
                float2 wA0 = Wp[(2 * k4) * HFC + c2];
                float2 wB0 = Wp[(2 * k4 + 1) * HFC + c2];
                float2 wA1 = Wp[(2 * k4) * HFC + c2 + 64];
                float2 wB1 = Wp[(2 * k4 + 1) * HFC + c2 + 64];
                #pragma unroll
                for (int i = 0; i < 16; i++) {
                    float4 xv = *(const float4*)&xs[(row0 + i) * IN_N + 4 * k4];
                    float2 lo = make_float2(xv.x, xv.y);
                    float2 hi = make_float2(xv.z, xv.w);
                    acc0[i] = ffma2(lo, wA0, acc0[i]);
                    acc0[i] = ffma2(hi, wB0, acc0[i]);
                    acc1[i] = ffma2(lo, wA1, acc1[i]);
                    acc1[i] = ffma2(hi, wB1, acc1[i]);
                }
            }
            int gn = min(16, nrows - row0);
            for (int i = 0; i < gn; i++) {
                size_t ro = (size_t)(base + row0 + i) * HFC;
                O[ro + c2]      = acc0[i].x + acc0[i].y + b0;
                O[ro + c2 + 64] = acc1[i].x + acc1[i].y + b1;
            }
        }
    }
}

// ---------------------------------------------------------------------------
// 2) per-edge: f_out = lrelu(f_ni[src] + f_nj[dst] + efeats@W_fij + bias),
//    write f_out (streaming), raw logits to g_ex. No atomics.
//    Software-pipelined: next tile's efeats+indices prefetched into registers
//    during the current tile's GEMM; double-buffered SMEM; 1 sync per tile.
// ---------------------------------------------------------------------------
#define EPB1 8
__global__ __launch_bounds__(128) void edge_pass1(
    const float* __restrict__ ef, const int* __restrict__ src,
    const int* __restrict__ dst, const float* __restrict__ Wf,
    const float* __restrict__ attn, const float* __restrict__ bias,
    float* __restrict__ fout, int nTiles)
{
    const int c = threadIdx.x;
    const int head = c >> 5;
    const int lane = c & 31;

    float2 wc2[IN_E / 2];
    #pragma unroll
    for (int k2 = 0; k2 < IN_E / 2; k2++)
        wc2[k2] = make_float2(Wf[(2 * k2) * HFC + c], Wf[(2 * k2 + 1) * HFC + c]);
    const float av = attn[head * 32 + lane];
    const float bv = bias[c];

    // EPB1*IN_E/4 = 128 float4 per tile == one per thread
    __shared__ float efs[2][EPB1][IN_E];
    __shared__ int sidx[2][EPB1], didx[2][EPB1];

    const long long tstep = gridDim.x;
    long long tile = blockIdx.x;
    if (tile >= nTiles) return;

    // prefetch first tile into registers
    float4 pf; int ps = 0, pd = 0;
    {
        long long e0 = tile * EPB1;
        pf = __ldcs(((const float4*)(ef + (size_t)e0 * IN_E)) + c);
        if (c < EPB1) ps = src[e0 + c];
        else if (c >= 32 && c < 32 + EPB1) pd = dst[e0 + (c - 32)];
    }

    int buf = 0;
    for (; tile < nTiles; tile += tstep, buf ^= 1) {
        long long e0 = tile * EPB1;
        // commit prefetched tile to SMEM
        ((float4*)efs[buf])[c] = pf;
        if (c < EPB1) sidx[buf][c] = ps;
        else if (c >= 32 && c < 32 + EPB1) didx[buf][c - 32] = pd;
        __syncthreads();

        // issue next tile's prefetch (overlaps gathers + GEMM below)
        long long nt = tile + tstep;
        if (nt < nTiles) {
            long long ne0 = nt * EPB1;
            pf = __ldcs(((const float4*)(ef + (size_t)ne0 * IN_E)) + c);
            if (c < EPB1) ps = src[ne0 + c];
            else if (c >= 32 && c < 32 + EPB1) pd = dst[ne0 + (c - 32)];
        }

        // issue all fni/fnj gathers up-front (MLP 16, overlap the GEMM)
        float fv[EPB1], gv[EPB1];
        #pragma unroll
        for (int j = 0; j < EPB1; j++) {
            fv[j] = __ldg(&g_fni[(size_t)sidx[buf][j] * HFC + c]);
            gv[j] = __ldg(&g_fnj[(size_t)didx[buf][j] * HFC + c]);
        }

        float2 acc[EPB1];
        #pragma unroll
        for (int j = 0; j < EPB1; j++) acc[j] = make_float2(0.f, 0.f);

        #pragma unroll 4
        for (int k4 = 0; k4 < IN_E / 4; k4++) {
            #pragma unroll
            for (int j = 0; j < EPB1; j++) {
                float4 xv = *(const float4*)&efs[buf][j][4 * k4];
                acc[j] = ffma2(make_float2(xv.x, xv.y), wc2[2 * k4], acc[j]);
                acc[j] = ffma2(make_float2(xv.z, xv.w), wc2[2 * k4 + 1], acc[j]);
            }
        }

        // tail: compute + store all v, then interleaved shuffle reductions
        float t[EPB1];
        #pragma unroll
        for (int j = 0; j < EPB1; j++) {
            float v = acc[j].x + acc[j].y + bv + fv[j] + gv[j];
            v = (v > 0.0f) ? v : 0.01f * v;               // leaky relu
            __stcs(&fout[(size_t)(e0 + j) * HFC + c], v); // write-once: stream
            t[j] = v * av;
        }
        #pragma unroll
        for (int o = 16; o > 0; o >>= 1) {
            #pragma unroll
            for (int j = 0; j < EPB1; j++)
                t[j] += __shfl_xor_sync(0xffffffffu, t[j], o);
        }
        if (lane == 0) {
            #pragma unroll
            for (int j = 0; j < EPB1; j++)
                g_ex[(e0 + j) * 4 + head] = t[j];
        }
    }
}

// remainder edges (E % EPB1); rarely used
__global__ __launch_bounds__(128) void edge_rem(
    const float* __restrict__ ef, const int* __restrict__ src,
    const int* __restrict__ dst, const float* __restrict__ Wf,
    const float* __restrict__ attn, const float* __restrict__ bias,
    float* __restrict__ fout, int e_begin, int E)
{
    const int c = threadIdx.x;
    const int head = c >> 5;
    const int lane = c & 31;
    const float av = attn[head * 32 + lane];
    for (int e = e_begin; e < E; e++) {
        int s = src[e], d = dst[e];
        float acc = bias[c];
        for (int k = 0; k < IN_E; k++)
            acc = fmaf(ef[(size_t)e * IN_E + k], Wf[k * HFC + c], acc);
        float v = acc + g_fni[(size_t)s * HFC + c] + g_fnj[(size_t)d * HFC + c];
        v = (v > 0.0f) ? v : 0.01f * v;
        fout[(size_t)e * HFC + c] = v;
        float t = v * av;
        #pragma unroll
        for (int o = 16; o > 0; o >>= 1)
            t += __shfl_xor_sync(0xffffffffu, t, o);
        if (lane == 0)
            g_ex[(size_t)e * 4 + head] = t;
    }
}

// ---------------------------------------------------------------------------
// 3) fused per-node softmax + aggregation. One warp per node, no atomics.
//    h_out[d] = sum_e softmax_e(logit) * h[src[e]]   (per head)
// ---------------------------------------------------------------------------
#define AGG_WARPS 8
#define AGG_CAP 128
__global__ __launch_bounds__(256) void agg(
    const int* __restrict__ src, float* __restrict__ hout, int N)
{
    __shared__ float sa[AGG_WARPS][AGG_CAP * 4];   // exp values per edge/head
    __shared__ int   ss[AGG_WARPS][AGG_CAP];       // src ids
    const int w = threadIdx.x >> 5;
    const int lane = threadIdx.x & 31;
    const int d = blockIdx.x * AGG_WARPS + w;
    if (d >= N) return;

    const int start = g_rowptr[d];
    const int deg = g_rowptr[d + 1] - start;
    const float NEG = __int_as_float(0xff800000);   // -inf

    // phase 1a: per-head max over incoming edges
    float4 m4 = make_float4(NEG, NEG, NEG, NEG);
    for (int t = lane; t < deg; t += 32) {
        int eid = g_cidx[start + t];
        float4 l4 = *(const float4*)&g_ex[(size_t)eid * 4];
        m4.x = fmaxf(m4.x, l4.x); m4.y = fmaxf(m4.y, l4.y);
        m4.z = fmaxf(m4.z, l4.z); m4.w = fmaxf(m4.w, l4.w);
    }
    #pragma unroll
    for (int o = 16; o > 0; o >>= 1) {
        m4.x = fmaxf(m4.x, __shfl_xor_sync(0xffffffffu, m4.x, o));
        m4.y = fmaxf(m4.y, __shfl_xor_sync(0xffffffffu, m4.y, o));
        m4.z = fmaxf(m4.z, __shfl_xor_sync(0xffffffffu, m4.z, o));
        m4.w = fmaxf(m4.w, __shfl_xor_sync(0xffffffffu, m4.w, o));
    }

    // phase 1b: exp + sum, stash exp values and src ids in SMEM
    float4 s4 = make_float4(0.f, 0.f, 0.f, 0.f);
    for (int t = lane; t < deg; t += 32) {
        int eid = g_cidx[start + t];
        float4 l4 = *(const float4*)&g_ex[(size_t)eid * 4];
        float4 e4 = make_float4(__expf(l4.x - m4.x), __expf(l4.y - m4.y),
                                __expf(l4.z - m4.z), __expf(l4.w - m4.w));
        s4.x += e4.x; s4.y += e4.y; s4.z += e4.z; s4.w += e4.w;
        if (t < AGG_CAP) {
            *(float4*)&sa[w][t * 4] = e4;
            ss[w][t] = src[eid];
        }
    }
    #pragma unroll
    for (int o = 16; o > 0; o >>= 1) {
        s4.x += __shfl_xor_sync(0xffffffffu, s4.x, o);
        s4.y += __shfl_xor_sync(0xffffffffu, s4.y, o);
        s4.z += __shfl_xor_sync(0xffffffffu, s4.z, o);
        s4.w += __shfl_xor_sync(0xffffffffu, s4.w, o);
    }
    __syncwarp();

    const int head = lane >> 3;
    const float inv = __fdividef(1.0f, compsel(s4, head));
    const float mh = compsel(m4, head);

    // phase 2: aggregate h[src]*a with MLP-4 grouped gathers
    float4 acc = make_float4(0.f, 0.f, 0.f, 0.f);
    for (int t0 = 0; t0 < deg; t0 += 4) {
        int n = min(4, deg - t0);
        float a[4]; int s[4];
        #pragma unroll
        for (int r = 0; r < 4; r++) {
            if (r < n) {
                int t = t0 + r;
                if (t < AGG_CAP) {
                    a[r] = sa[w][t * 4 + head] * inv;
                    s[r] = ss[w][t];
                } else {                           // overflow fallback (rare)
                    int eid = g_cidx[start + t];
                    float4 l4 = *(const float4*)&g_ex[(size_t)eid * 4];
                    a[r] = __expf(compsel(l4, head) - mh) * inv;
                    s[r] = src[eid];
                }
            }
        }
        float4 hv[4];
        #pragma unroll
        for (int r = 0; r < 4; r++)
            if (r < n) hv[r] = __ldg(&((const float4*)(g_h + (size_t)s[r] * HFC))[lane]);
        #pragma unroll
        for (int r = 0; r < 4; r++) {
            if (r < n) {
                acc.x = fmaf(hv[r].x, a[r], acc.x);
                acc.y = fmaf(hv[r].y, a[r], acc.y);
                acc.z = fmaf(hv[r].z, a[r], acc.z);
                acc.w = fmaf(hv[r].w, a[r], acc.w);
            }
        }
    }
    ((float4*)(hout + (size_t)d * HFC))[lane] = acc;
}

// ---------------------------------------------------------------------------
extern "C" void kernel_launch(void* const* d_in, const int* in_sizes, int n_in,
                              void* d_out, int out_size)
{
    const float* nfeats = (const float*)d_in[0];
    const float* efeats = (const float*)d_in[1];
    const int*   src    = (const int*)d_in[2];
    const int*   dst    = (const int*)d_in[3];
    const float* W_node = (const float*)d_in[4];
    const float* b_node = (const float*)d_in[5];
    const float* W_ni   = (const float*)d_in[6];
    const float* W_nj   = (const float*)d_in[7];
    const float* W_fij  = (const float*)d_in[8];
    const float* attn   = (const float*)d_in[9];
    const float* bias   = (const float*)d_in[10];

    const int N = in_sizes[0] / IN_N;   // 100000
    const int E = in_sizes[2];          // 1000000

    float* h_out = (float*)d_out;                       // [N, 128]
    float* f_out = (float*)d_out + (size_t)N * HFC;     // [E, 128]

    int nb = (N + 255) / 256;
    int nTiles = E / EPB1;

    // launch order chosen so edge_pass1 is the 4th launch (ncu -s capture slot)
    setup_kernel<<<512, 256>>>(W_ni, W_nj, W_node, N);            // 1
    node_proj<<<(N + 63) / 64, 128>>>(nfeats, b_node, N);         // 2
    csr_count<<<(E + 255) / 256, 256>>>(dst, E);                  // 3
    if (nTiles > 0)
        edge_pass1<<<148 * 8, 128>>>(efeats, src, dst, W_fij,     // 4
                                     attn, bias, f_out, nTiles);
    scan_a     <<<nb, 256>>>(N);                                  // 5
    scan_b     <<<1, 512>>>(nb);                                  // 6
    scan_c     <<<nb, 256>>>(N, E);                               // 7
    csr_scatter<<<(E + 255) / 256, 256>>>(dst, E);                // 8
    if (E % EPB1)
        edge_rem<<<1, 128>>>(efeats, src, dst, W_fij, attn, bias,
                             f_out, nTiles * EPB1, E);
    agg<<<(N + AGG_WARPS - 1) / AGG_WARPS, 256>>>(src, h_out, N); // 9
}